// round 10
// baseline (speedup 1.0000x reference)
#include <cuda_runtime.h>
#include <cuda_bf16.h>

typedef unsigned int u32;

#define Tq 28
#define Iq 28
#define Hq 128
#define Cq 10

// SMEM map (bytes): W0h@0 W0l@32768 WIh@65536 WIl@98304 WHh@131072 WHl@163840 (256B-row swizzle)
// X0h@196608 X0l@204800 (64B-row swizzle) | exch@212992(16K; FC reuse: fcw@212992 part@218112)
// b0@229376 b1@229888
#define OFF_X0H 196608
#define OFF_X0L 204800
#define OFF_EX  212992
#define OFF_PART 218112
#define OFF_B0 229376
#define OFF_B1 229888
#define SMEM_DYN 230400

static __device__ __forceinline__ u32 smem_u32(const void* p) {
    u32 a; asm("{ .reg .u64 t; cvta.to.shared.u64 t, %1; cvt.u32.u64 %0, t; }" : "=r"(a) : "l"(p));
    return a;
}
static __device__ __forceinline__ float tanh_fast(float x) {
    float ax = fabsf(x), e = __expf(-2.f * ax);
    return copysignf(__fdividef(1.f - e, 1.f + e), x);
}
static __device__ __forceinline__ u32 pack_bf16x2(float lo, float hi) {
    u32 r; asm("cvt.rn.bf16x2.f32 %0, %1, %2;" : "=r"(r) : "f"(hi), "f"(lo)); return r;
}
static __device__ __forceinline__ float lo16f(u32 p) { return __uint_as_float(p << 16); }
static __device__ __forceinline__ float hi16f(u32 p) { return __uint_as_float(p & 0xFFFF0000u); }

static __device__ __forceinline__ void mma_bf16(float (&d)[4], const u32 (&a)[4], u32 b0, u32 b1) {
    asm volatile(
        "mma.sync.aligned.m16n8k16.row.col.f32.bf16.bf16.f32 "
        "{%0,%1,%2,%3}, {%4,%5,%6,%7}, {%8,%9}, {%0,%1,%2,%3};"
        : "+f"(d[0]), "+f"(d[1]), "+f"(d[2]), "+f"(d[3])
        : "r"(a[0]), "r"(a[1]), "r"(a[2]), "r"(a[3]), "r"(b0), "r"(b1));
}
#define LDMX4(r0, r1, r2, r3, addr) \
    asm volatile("ldmatrix.sync.aligned.m8n8.x4.shared.b16 {%0,%1,%2,%3}, [%4];" \
        : "=r"(r0), "=r"(r1), "=r"(r2), "=r"(r3) : "r"(addr))
#define STS128(addr, r) \
    asm volatile("st.shared.v4.b32 [%0], {%1,%2,%3,%4};" \
        :: "r"(addr), "r"((r)[0]), "r"((r)[1]), "r"((r)[2]), "r"((r)[3]) : "memory")
#define LDS128(r, addr) \
    asm volatile("ld.shared.v4.b32 {%0,%1,%2,%3}, [%4];" \
        : "=r"((r)[0]), "=r"((r)[1]), "=r"((r)[2]), "=r"((r)[3]) : "r"(addr) : "memory")
#define BARS(id) asm volatile("bar.sync %0, 64;" :: "r"(id) : "memory")

// D[8][4] += A(hi,lo) @ W(hi,lo)^T over this warp's 64 j-cols. 256B-row swizzled tile.
static __device__ __forceinline__ void gemm3h(float (&D)[8][4],
                                              const u32 (&Ah)[8][4], const u32 (&Al)[8][4],
                                              u32 whb, u32 wlb, u32 hsR, u32 sw56)
{
    #pragma unroll
    for (int kt = 0; kt < 8; kt++) {
        u32 cx = ((u32)(kt * 32) ^ sw56) + hsR;
        #pragma unroll
        for (int np = 0; np < 4; np++) {
            u32 off = (u32)(np * 4096) + cx;
            u32 bh0, bh1, bh2, bh3, bl0, bl1, bl2, bl3;
            LDMX4(bh0, bh1, bh2, bh3, whb + off);
            LDMX4(bl0, bl1, bl2, bl3, wlb + off);
            mma_bf16(D[2 * np],     Ah[kt], bh0, bh1);
            mma_bf16(D[2 * np],     Al[kt], bh0, bh1);
            mma_bf16(D[2 * np],     Ah[kt], bl0, bl1);
            mma_bf16(D[2 * np + 1], Ah[kt], bh2, bh3);
            mma_bf16(D[2 * np + 1], Al[kt], bh2, bh3);
            mma_bf16(D[2 * np + 1], Ah[kt], bl2, bl3);
        }
    }
}
// x GEMM: K=32 (2 chunks), 64B-row swizzled X tile.
static __device__ __forceinline__ void gemm_x(float (&D)[8][4],
                                              const u32 (&Ah)[2][4], const u32 (&Al)[2][4],
                                              u32 xhb, u32 xlb, u32 hsX, u32 sw5x)
{
    #pragma unroll
    for (int kt = 0; kt < 2; kt++) {
        u32 cx = ((u32)(kt * 32) ^ sw5x) + hsX;
        #pragma unroll
        for (int np = 0; np < 4; np++) {
            u32 off = (u32)(np * 1024) + cx;
            u32 bh0, bh1, bh2, bh3, bl0, bl1, bl2, bl3;
            LDMX4(bh0, bh1, bh2, bh3, xhb + off);
            LDMX4(bl0, bl1, bl2, bl3, xlb + off);
            mma_bf16(D[2 * np],     Ah[kt], bh0, bh1);
            mma_bf16(D[2 * np],     Al[kt], bh0, bh1);
            mma_bf16(D[2 * np],     Ah[kt], bl0, bl1);
            mma_bf16(D[2 * np + 1], Ah[kt], bh2, bh3);
            mma_bf16(D[2 * np + 1], Al[kt], bh2, bh3);
            mma_bf16(D[2 * np + 1], Ah[kt], bl2, bl3);
        }
    }
}
// tanh epilogue: D (own 64 cols) -> hi/lo A-frag chunks [base..base+3]
static __device__ __forceinline__ void tanh_pack(const float (&D)[8][4],
                                                 u32 (&hh)[8][4], u32 (&hl)[8][4], int base)
{
    #pragma unroll
    for (int ktl = 0; ktl < 4; ktl++) {
        #pragma unroll
        for (int o = 0; o < 2; o++) {
            int nt = 2 * ktl + o;
            float v0 = tanh_fast(D[nt][0]), v1 = tanh_fast(D[nt][1]);
            float v2 = tanh_fast(D[nt][2]), v3 = tanh_fast(D[nt][3]);
            u32 p01 = pack_bf16x2(v0, v1), p23 = pack_bf16x2(v2, v3);
            hh[base + ktl][2 * o] = p01;  hh[base + ktl][2 * o + 1] = p23;
            hl[base + ktl][2 * o]     = pack_bf16x2(v0 - lo16f(p01), v1 - hi16f(p01));
            hl[base + ktl][2 * o + 1] = pack_bf16x2(v2 - lo16f(p23), v3 - hi16f(p23));
        }
    }
}
// pairwise hi/lo fragment exchange through SMEM
static __device__ __forceinline__ void xchg(u32 (&hh)[8][4], u32 (&hl)[8][4],
                                            u32 exOwn, u32 exOth, int own, int oth, int barid)
{
    #pragma unroll
    for (int k = 0; k < 4; k++) STS128(exOwn + k * 512, hh[own + k]);
    BARS(barid);
    #pragma unroll
    for (int k = 0; k < 4; k++) LDS128(hh[oth + k], exOth + k * 512);
    BARS(barid);
    #pragma unroll
    for (int k = 0; k < 4; k++) STS128(exOwn + k * 512, hl[own + k]);
    BARS(barid);
    #pragma unroll
    for (int k = 0; k < 4; k++) LDS128(hl[oth + k], exOth + k * 512);
    BARS(barid);
}

__global__ void __launch_bounds__(256, 1) rnn_fused(
    const float* __restrict__ x,
    const float* __restrict__ W_ih0, const float* __restrict__ W_hh0,
    const float* __restrict__ b_ih0, const float* __restrict__ b_hh0,
    const float* __restrict__ W_ih1, const float* __restrict__ W_hh1,
    const float* __restrict__ b_ih1, const float* __restrict__ b_hh1,
    const float* __restrict__ fc_w,  const float* __restrict__ fc_b,
    float* __restrict__ out)
{
    extern __shared__ char dyn[];
    const int tid = threadIdx.x;
    const int wid = tid >> 5, lane = tid & 31;
    const int rg = wid >> 1, jh = wid & 1;   // partners on DIFFERENT SMSPs now
    const int g = lane >> 2, p = lane & 3;

    // ---- init: W tiles bf16 hi/lo, swizzled ----
    {
        const float* Ws[3] = { W_hh0, W_ih1, W_hh1 };
        #pragma unroll
        for (int m = 0; m < 3; m++) {
            char* dh = dyn + (2 * m) * 32768;
            char* dl = dyn + (2 * m + 1) * 32768;
            const float* W = Ws[m];
            for (int i = tid; i < Hq * Hq; i += 256) {
                int j = i >> 7, k = i & 127;
                float v = W[i];
                __nv_bfloat16 hb = __float2bfloat16(v);
                u32 a = (u32)(j * 256) + (u32)((2 * k) ^ ((j & 7) << 4));
                *(__nv_bfloat16*)(dh + a) = hb;
                *(__nv_bfloat16*)(dl + a) = __float2bfloat16(v - __bfloat162float(hb));
            }
        }
        for (int i = tid; i < Hq * 32; i += 256) {   // X tiles [j][k pad32]
            int j = i >> 5, k = i & 31;
            float v = (k < Iq) ? W_ih0[j * Iq + k] : 0.0f;
            __nv_bfloat16 hb = __float2bfloat16(v);
            u32 a = (u32)(j * 64) + (u32)((2 * k) ^ ((j & 3) << 4));
            *(__nv_bfloat16*)(dyn + OFF_X0H + a) = hb;
            *(__nv_bfloat16*)(dyn + OFF_X0L + a) = __float2bfloat16(v - __bfloat162float(hb));
        }
        float* b0s = (float*)(dyn + OFF_B0);
        float* b1s = (float*)(dyn + OFF_B1);
        for (int i = tid; i < Hq; i += 256) {
            b0s[i] = b_ih0[i] + b_hh0[i];
            b1s[i] = b_ih1[i] + b_hh1[i];
        }
    }
    __syncthreads();

    const u32 smb = smem_u32(dyn);
    const u32 r    = (u32)((((lane >> 4) & 1) * 8) + (lane & 7));
    const u32 h16  = (u32)(((lane >> 3) & 1) * 16);
    const u32 swzR = (u32)((lane & 7) << 4);
    const u32 hsR  = r * 256 + (h16 ^ (swzR & 16));
    const u32 sw56 = swzR & 96;
    const u32 swzX = (u32)((lane & 3) << 4);
    const u32 hsX  = r * 64 + (h16 ^ (swzX & 16));
    const u32 sw5x = swzX & 32;

    const u32 W0H = smb + (u32)(jh * 16384),           W0L = smb + 32768  + (u32)(jh * 16384);
    const u32 WIH = smb + 65536 + (u32)(jh * 16384),   WIL = smb + 98304  + (u32)(jh * 16384);
    const u32 WHH = smb + 131072 + (u32)(jh * 16384),  WHL = smb + 163840 + (u32)(jh * 16384);
    const u32 X0H = smb + OFF_X0H + (u32)(jh * 4096),  X0L = smb + OFF_X0L + (u32)(jh * 4096);
    const u32 exOwn = smb + OFF_EX + (u32)((((rg * 2 + jh) * 4) * 32 + lane) * 16);
    const u32 exOth = smb + OFF_EX + (u32)((((rg * 2 + 1 - jh) * 4) * 32 + lane) * 16);
    const int own = jh * 4, oth = (1 - jh) * 4, barid = rg + 1;

    const float* b0s = (float*)(dyn + OFF_B0);
    const float* b1s = (float*)(dyn + OFF_B1);
    const size_t rowA = ((size_t)blockIdx.x * 4 + rg) * 16 + g;
    const float* xA = x + rowA * Tq * Iq;
    const float* xB = x + (rowA + 8) * Tq * Iq;

    u32 h0h[8][4], h0l[8][4], h1h[8][4], h1l[8][4];
    float D0[8][4], D1[8][4];

    // x loader (for timestep tt) -> xv[8] float2
    #define LOADX(xv, tt) do { \
        const float* at = xA + (tt) * Iq; \
        const float* bt = xB + (tt) * Iq; \
        xv[0] = *(const float2*)(at + 2 * p);       xv[1] = *(const float2*)(bt + 2 * p); \
        xv[2] = *(const float2*)(at + 8 + 2 * p);   xv[3] = *(const float2*)(bt + 8 + 2 * p); \
        xv[4] = *(const float2*)(at + 16 + 2 * p);  xv[5] = *(const float2*)(bt + 16 + 2 * p); \
        xv[6] = (p < 2) ? *(const float2*)(at + 24 + 2 * p) : make_float2(0.f, 0.f); \
        xv[7] = (p < 2) ? *(const float2*)(bt + 24 + 2 * p) : make_float2(0.f, 0.f); \
    } while (0)
    #define CVTX(xh, xl, xv) do { \
        _Pragma("unroll") \
        for (int q = 0; q < 8; q++) { \
            u32 hu = pack_bf16x2(xv[q].x, xv[q].y); \
            xh[q >> 2][q & 3] = hu; \
            xl[q >> 2][q & 3] = pack_bf16x2(xv[q].x - lo16f(hu), xv[q].y - hi16f(hu)); \
        } \
    } while (0)
    #define D_INIT(D, bs) do { \
        _Pragma("unroll") \
        for (int nt = 0; nt < 8; nt++) { \
            float2 bv = *(const float2*)&(bs)[jh * 64 + nt * 8 + p * 2]; \
            (D)[nt][0] = bv.x; (D)[nt][1] = bv.y; (D)[nt][2] = bv.x; (D)[nt][3] = bv.y; \
        } \
    } while (0)

    // ---- prologue: h0(0) = tanh(b0 + x(0)@Wih0^T) ----
    {
        float2 xv[8];
        u32 xh[2][4], xl[2][4];
        LOADX(xv, 0);
        CVTX(xh, xl, xv);
        D_INIT(D0, b0s);
        gemm_x(D0, xh, xl, X0H, X0L, hsX, sw5x);
        tanh_pack(D0, h0h, h0l, own);
        xchg(h0h, h0l, exOwn, exOth, own, oth, barid);
    }

    // ---- pipelined main loop: one step = combined gemm phase + combined epilogue ----
    for (int t = 0; t < Tq; t++) {
        const bool hasNext = (t < Tq - 1);
        float2 xv[8];
        if (hasNext) LOADX(xv, t + 1);          // LDG latency hides under D1 gemms

        // D1 = b1 + h0(t)@Wih1^T + h1(t-1)@Whh1^T
        D_INIT(D1, b1s);
        gemm3h(D1, h0h, h0l, WIH, WIL, hsR, sw56);
        if (t > 0) gemm3h(D1, h1h, h1l, WHH, WHL, hsR, sw56);

        if (hasNext) {
            // D0 = b0 + x(t+1)@Wih0^T + h0(t)@Whh0^T  (independent of D1)
            u32 xh[2][4], xl[2][4];
            CVTX(xh, xl, xv);
            D_INIT(D0, b0s);
            gemm3h(D0, h0h, h0l, W0H, W0L, hsR, sw56);
            gemm_x(D0, xh, xl, X0H, X0L, hsX, sw5x);

            // combined epilogue + back-to-back exchanges
            tanh_pack(D1, h1h, h1l, own);
            tanh_pack(D0, h0h, h0l, own);       // h0(t) frags dead now, safe to overwrite
            xchg(h1h, h1l, exOwn, exOth, own, oth, barid);
            xchg(h0h, h0l, exOwn, exOth, own, oth, barid);
        } else {
            // final step: keep fp32 tanh for FC
            #pragma unroll
            for (int nt = 0; nt < 8; nt++)
                #pragma unroll
                for (int q = 0; q < 4; q++) D1[nt][q] = tanh_fast(D1[nt][q]);
        }
    }

    // ---- FC: out = h1 @ fc_w^T + fc_b ----
    __syncthreads();
    float* fcs  = (float*)(dyn + OFF_EX);
    float* part = (float*)(dyn + OFF_PART);
    for (int i = tid; i < Cq * Hq; i += 256) fcs[i] = fc_w[i];
    __syncthreads();

    float accA[Cq], accB[Cq];
    #pragma unroll
    for (int c = 0; c < Cq; c++) { accA[c] = 0.f; accB[c] = 0.f; }
    #pragma unroll
    for (int nt = 0; nt < 8; nt++) {
        int j = jh * 64 + nt * 8 + p * 2;
        #pragma unroll
        for (int c = 0; c < Cq; c++) {
            float2 fw = *(const float2*)&fcs[c * Hq + j];
            accA[c] = fmaf(D1[nt][0], fw.x, fmaf(D1[nt][1], fw.y, accA[c]));
            accB[c] = fmaf(D1[nt][2], fw.x, fmaf(D1[nt][3], fw.y, accB[c]));
        }
    }
    #pragma unroll
    for (int c = 0; c < Cq; c++) {
        accA[c] += __shfl_xor_sync(0xFFFFFFFFu, accA[c], 1);
        accA[c] += __shfl_xor_sync(0xFFFFFFFFu, accA[c], 2);
        accB[c] += __shfl_xor_sync(0xFFFFFFFFu, accB[c], 1);
        accB[c] += __shfl_xor_sync(0xFFFFFFFFu, accB[c], 2);
    }
    if (p == 0) {
        int base = (rg * 2 + jh) * 16;
        #pragma unroll
        for (int c = 0; c < Cq; c++) {
            part[(base + g) * Cq + c]     = accA[c];
            part[(base + g + 8) * Cq + c] = accB[c];
        }
    }
    __syncthreads();
    for (int i = tid; i < 64 * Cq; i += 256) {
        int row = i / Cq, c = i - row * Cq;
        int rg2 = row >> 4, rr = row & 15;
        float v = fc_b[c] + part[((rg2 * 2) * 16 + rr) * Cq + c]
                          + part[((rg2 * 2 + 1) * 16 + rr) * Cq + c];
        out[((size_t)blockIdx.x * 64 + row) * Cq + c] = v;
    }
}

extern "C" void kernel_launch(void* const* d_in, const int* in_sizes, int n_in,
                              void* d_out, int out_size) {
    const float* x     = (const float*)d_in[0];
    const float* W_ih0 = (const float*)d_in[1];
    const float* W_hh0 = (const float*)d_in[2];
    const float* b_ih0 = (const float*)d_in[3];
    const float* b_hh0 = (const float*)d_in[4];
    const float* W_ih1 = (const float*)d_in[5];
    const float* W_hh1 = (const float*)d_in[6];
    const float* b_ih1 = (const float*)d_in[7];
    const float* b_hh1 = (const float*)d_in[8];
    const float* fc_w  = (const float*)d_in[9];
    const float* fc_b  = (const float*)d_in[10];
    float* out = (float*)d_out;

    cudaFuncSetAttribute(rnn_fused, cudaFuncAttributeMaxDynamicSharedMemorySize, SMEM_DYN);
    rnn_fused<<<128, 256, SMEM_DYN>>>(x, W_ih0, W_hh0, b_ih0, b_hh0,
                                      W_ih1, W_hh1, b_ih1, b_hh1, fc_w, fc_b, out);
}

// round 11
// speedup vs baseline: 1.0862x; 1.0862x over previous
#include <cuda_runtime.h>
#include <cuda_bf16.h>

typedef unsigned int u32;

#define Tq 28
#define Iq 28
#define Hq 128
#define Cq 10

// SMEM map (bytes): W0h@0 W0l@32768 WIh@65536 WIl@98304 WHh@131072 WHl@163840 (256B-row swizzle)
// X0h@196608 X0l@204800 (64B-row swizzle) | exch@212992(16K; FC reuse: fcw@212992 part@218112)
// b0@229376 b1@229888
#define OFF_X0H 196608
#define OFF_X0L 204800
#define OFF_EX  212992
#define OFF_PART 218112
#define OFF_B0 229376
#define OFF_B1 229888
#define SMEM_DYN 230400

static __device__ __forceinline__ u32 smem_u32(const void* p) {
    u32 a; asm("{ .reg .u64 t; cvta.to.shared.u64 t, %1; cvt.u32.u64 %0, t; }" : "=r"(a) : "l"(p));
    return a;
}
static __device__ __forceinline__ float tanh_fast(float x) {
    float ax = fabsf(x), e = __expf(-2.f * ax);
    return copysignf(__fdividef(1.f - e, 1.f + e), x);
}
static __device__ __forceinline__ u32 pack_bf16x2(float lo, float hi) {
    u32 r; asm("cvt.rn.bf16x2.f32 %0, %1, %2;" : "=r"(r) : "f"(hi), "f"(lo)); return r;
}
static __device__ __forceinline__ float lo16f(u32 p) { return __uint_as_float(p << 16); }
static __device__ __forceinline__ float hi16f(u32 p) { return __uint_as_float(p & 0xFFFF0000u); }

static __device__ __forceinline__ void mma_bf16(float (&d)[4], const u32 (&a)[4], u32 b0, u32 b1) {
    asm volatile(
        "mma.sync.aligned.m16n8k16.row.col.f32.bf16.bf16.f32 "
        "{%0,%1,%2,%3}, {%4,%5,%6,%7}, {%8,%9}, {%0,%1,%2,%3};"
        : "+f"(d[0]), "+f"(d[1]), "+f"(d[2]), "+f"(d[3])
        : "r"(a[0]), "r"(a[1]), "r"(a[2]), "r"(a[3]), "r"(b0), "r"(b1));
}
#define LDMX4(r0, r1, r2, r3, addr) \
    asm volatile("ldmatrix.sync.aligned.m8n8.x4.shared.b16 {%0,%1,%2,%3}, [%4];" \
        : "=r"(r0), "=r"(r1), "=r"(r2), "=r"(r3) : "r"(addr))
#define STS128(addr, r) \
    asm volatile("st.shared.v4.b32 [%0], {%1,%2,%3,%4};" \
        :: "r"(addr), "r"((r)[0]), "r"((r)[1]), "r"((r)[2]), "r"((r)[3]) : "memory")
#define LDS128(r, addr) \
    asm volatile("ld.shared.v4.b32 {%0,%1,%2,%3}, [%4];" \
        : "=r"((r)[0]), "=r"((r)[1]), "=r"((r)[2]), "=r"((r)[3]) : "r"(addr) : "memory")
#define BARS(id) asm volatile("bar.sync %0, 64;" :: "r"(id) : "memory")

// D[8][4] += A(hi,lo) @ W(hi,lo)^T over this warp's 64 j-cols. 256B-row swizzled tile.
static __device__ __forceinline__ void gemm3h(float (&D)[8][4],
                                              const u32 (&Ah)[8][4], const u32 (&Al)[8][4],
                                              u32 whb, u32 wlb, u32 hsR, u32 sw56)
{
    #pragma unroll
    for (int kt = 0; kt < 8; kt++) {
        u32 cx = ((u32)(kt * 32) ^ sw56) + hsR;
        #pragma unroll
        for (int np = 0; np < 4; np++) {
            u32 off = (u32)(np * 4096) + cx;
            u32 bh0, bh1, bh2, bh3, bl0, bl1, bl2, bl3;
            LDMX4(bh0, bh1, bh2, bh3, whb + off);
            LDMX4(bl0, bl1, bl2, bl3, wlb + off);
            mma_bf16(D[2 * np],     Ah[kt], bh0, bh1);
            mma_bf16(D[2 * np],     Al[kt], bh0, bh1);
            mma_bf16(D[2 * np],     Ah[kt], bl0, bl1);
            mma_bf16(D[2 * np + 1], Ah[kt], bh2, bh3);
            mma_bf16(D[2 * np + 1], Al[kt], bh2, bh3);
            mma_bf16(D[2 * np + 1], Ah[kt], bl2, bl3);
        }
    }
}
// x GEMM: K=32 (2 chunks), 64B-row swizzled X tile.
static __device__ __forceinline__ void gemm_x(float (&D)[8][4],
                                              const u32 (&Ah)[2][4], const u32 (&Al)[2][4],
                                              u32 xhb, u32 xlb, u32 hsX, u32 sw5x)
{
    #pragma unroll
    for (int kt = 0; kt < 2; kt++) {
        u32 cx = ((u32)(kt * 32) ^ sw5x) + hsX;
        #pragma unroll
        for (int np = 0; np < 4; np++) {
            u32 off = (u32)(np * 1024) + cx;
            u32 bh0, bh1, bh2, bh3, bl0, bl1, bl2, bl3;
            LDMX4(bh0, bh1, bh2, bh3, xhb + off);
            LDMX4(bl0, bl1, bl2, bl3, xlb + off);
            mma_bf16(D[2 * np],     Ah[kt], bh0, bh1);
            mma_bf16(D[2 * np],     Al[kt], bh0, bh1);
            mma_bf16(D[2 * np],     Ah[kt], bl0, bl1);
            mma_bf16(D[2 * np + 1], Ah[kt], bh2, bh3);
            mma_bf16(D[2 * np + 1], Al[kt], bh2, bh3);
            mma_bf16(D[2 * np + 1], Ah[kt], bl2, bl3);
        }
    }
}
// tanh epilogue: D (own 64 cols) -> hi/lo A-frag chunks [base..base+3]
static __device__ __forceinline__ void tanh_pack(const float (&D)[8][4],
                                                 u32 (&hh)[8][4], u32 (&hl)[8][4], int base)
{
    #pragma unroll
    for (int ktl = 0; ktl < 4; ktl++) {
        #pragma unroll
        for (int o = 0; o < 2; o++) {
            int nt = 2 * ktl + o;
            float v0 = tanh_fast(D[nt][0]), v1 = tanh_fast(D[nt][1]);
            float v2 = tanh_fast(D[nt][2]), v3 = tanh_fast(D[nt][3]);
            u32 p01 = pack_bf16x2(v0, v1), p23 = pack_bf16x2(v2, v3);
            hh[base + ktl][2 * o] = p01;  hh[base + ktl][2 * o + 1] = p23;
            hl[base + ktl][2 * o]     = pack_bf16x2(v0 - lo16f(p01), v1 - hi16f(p01));
            hl[base + ktl][2 * o + 1] = pack_bf16x2(v2 - lo16f(p23), v3 - hi16f(p23));
        }
    }
}
// pairwise hi/lo fragment exchange through SMEM (own chunks -> partner's missing chunks)
static __device__ __forceinline__ void xchg(u32 (&hh)[8][4], u32 (&hl)[8][4],
                                            u32 exOwn, u32 exOth, int own, int oth, int barid)
{
    #pragma unroll
    for (int k = 0; k < 4; k++) STS128(exOwn + k * 512, hh[own + k]);
    BARS(barid);
    #pragma unroll
    for (int k = 0; k < 4; k++) LDS128(hh[oth + k], exOth + k * 512);
    BARS(barid);
    #pragma unroll
    for (int k = 0; k < 4; k++) STS128(exOwn + k * 512, hl[own + k]);
    BARS(barid);
    #pragma unroll
    for (int k = 0; k < 4; k++) LDS128(hl[oth + k], exOth + k * 512);
    BARS(barid);
}

__global__ void __launch_bounds__(256, 1) rnn_fused(
    const float* __restrict__ x,
    const float* __restrict__ W_ih0, const float* __restrict__ W_hh0,
    const float* __restrict__ b_ih0, const float* __restrict__ b_hh0,
    const float* __restrict__ W_ih1, const float* __restrict__ W_hh1,
    const float* __restrict__ b_ih1, const float* __restrict__ b_hh1,
    const float* __restrict__ fc_w,  const float* __restrict__ fc_b,
    float* __restrict__ out)
{
    extern __shared__ char dyn[];
    const int tid = threadIdx.x;
    const int wid = tid >> 5, lane = tid & 31;
    // Cross-SMSP pairing: partners (wid, wid^1) sit on different SMSPs, and each
    // SMSP hosts two warps from DIFFERENT pairs -> their phases drift and overlap.
    const int rg = wid >> 1, jh = wid & 1;
    const int g = lane >> 2, p = lane & 3;

    // ---- init: W tiles bf16 hi/lo, swizzled ----
    {
        const float* Ws[3] = { W_hh0, W_ih1, W_hh1 };
        #pragma unroll
        for (int m = 0; m < 3; m++) {
            char* dh = dyn + (2 * m) * 32768;
            char* dl = dyn + (2 * m + 1) * 32768;
            const float* W = Ws[m];
            for (int i = tid; i < Hq * Hq; i += 256) {
                int j = i >> 7, k = i & 127;
                float v = W[i];
                __nv_bfloat16 hb = __float2bfloat16(v);
                u32 a = (u32)(j * 256) + (u32)((2 * k) ^ ((j & 7) << 4));
                *(__nv_bfloat16*)(dh + a) = hb;
                *(__nv_bfloat16*)(dl + a) = __float2bfloat16(v - __bfloat162float(hb));
            }
        }
        for (int i = tid; i < Hq * 32; i += 256) {   // X tiles [j][k pad32]
            int j = i >> 5, k = i & 31;
            float v = (k < Iq) ? W_ih0[j * Iq + k] : 0.0f;
            __nv_bfloat16 hb = __float2bfloat16(v);
            u32 a = (u32)(j * 64) + (u32)((2 * k) ^ ((j & 3) << 4));
            *(__nv_bfloat16*)(dyn + OFF_X0H + a) = hb;
            *(__nv_bfloat16*)(dyn + OFF_X0L + a) = __float2bfloat16(v - __bfloat162float(hb));
        }
        float* b0s = (float*)(dyn + OFF_B0);
        float* b1s = (float*)(dyn + OFF_B1);
        for (int i = tid; i < Hq; i += 256) {
            b0s[i] = b_ih0[i] + b_hh0[i];
            b1s[i] = b_ih1[i] + b_hh1[i];
        }
    }
    __syncthreads();

    const u32 smb = smem_u32(dyn);
    const u32 r    = (u32)((((lane >> 4) & 1) * 8) + (lane & 7));
    const u32 h16  = (u32)(((lane >> 3) & 1) * 16);
    const u32 swzR = (u32)((lane & 7) << 4);
    const u32 hsR  = r * 256 + (h16 ^ (swzR & 16));
    const u32 sw56 = swzR & 96;
    const u32 swzX = (u32)((lane & 3) << 4);
    const u32 hsX  = r * 64 + (h16 ^ (swzX & 16));
    const u32 sw5x = swzX & 32;

    const u32 W0H = smb + (u32)(jh * 16384),           W0L = smb + 32768  + (u32)(jh * 16384);
    const u32 WIH = smb + 65536 + (u32)(jh * 16384),   WIL = smb + 98304  + (u32)(jh * 16384);
    const u32 WHH = smb + 131072 + (u32)(jh * 16384),  WHL = smb + 163840 + (u32)(jh * 16384);
    const u32 X0H = smb + OFF_X0H + (u32)(jh * 4096),  X0L = smb + OFF_X0L + (u32)(jh * 4096);
    const u32 exOwn = smb + OFF_EX + (u32)((((rg * 2 + jh) * 4) * 32 + lane) * 16);
    const u32 exOth = smb + OFF_EX + (u32)((((rg * 2 + 1 - jh) * 4) * 32 + lane) * 16);
    const int own = jh * 4, oth = (1 - jh) * 4, barid = rg + 1;

    const float* b0s = (float*)(dyn + OFF_B0);
    const float* b1s = (float*)(dyn + OFF_B1);
    const size_t rowA = ((size_t)blockIdx.x * 4 + rg) * 16 + g;
    const float* xA = x + rowA * Tq * Iq;
    const float* xB = x + (rowA + 8) * Tq * Iq;

    u32 h0h[8][4], h0l[8][4], h1h[8][4], h1l[8][4];
    float D[8][4];

    for (int t = 0; t < Tq; t++) {
        // x A-frags (K=32, rows g/g+8); LDG latency hides under the layer-0 gemm below
        u32 xh[2][4], xl[2][4];
        {
            const float* at = xA + t * Iq;
            const float* bt = xB + t * Iq;
            float2 xv[8];
            xv[0] = *(const float2*)(at + 2 * p);       xv[1] = *(const float2*)(bt + 2 * p);
            xv[2] = *(const float2*)(at + 8 + 2 * p);   xv[3] = *(const float2*)(bt + 8 + 2 * p);
            xv[4] = *(const float2*)(at + 16 + 2 * p);  xv[5] = *(const float2*)(bt + 16 + 2 * p);
            xv[6] = (p < 2) ? *(const float2*)(at + 24 + 2 * p) : make_float2(0.f, 0.f);
            xv[7] = (p < 2) ? *(const float2*)(bt + 24 + 2 * p) : make_float2(0.f, 0.f);
            #pragma unroll
            for (int q = 0; q < 8; q++) {
                u32 hu = pack_bf16x2(xv[q].x, xv[q].y);
                xh[q >> 2][q & 3] = hu;
                xl[q >> 2][q & 3] = pack_bf16x2(xv[q].x - lo16f(hu), xv[q].y - hi16f(hu));
            }
        }

        // layer 0: D = b0 + h0@W0^T + x@Wih0^T
        #pragma unroll
        for (int nt = 0; nt < 8; nt++) {
            float2 bv = *(const float2*)&b0s[jh * 64 + nt * 8 + p * 2];
            D[nt][0] = bv.x; D[nt][1] = bv.y; D[nt][2] = bv.x; D[nt][3] = bv.y;
        }
        if (t > 0) gemm3h(D, h0h, h0l, W0H, W0L, hsR, sw56);
        gemm_x(D, xh, xl, X0H, X0L, hsX, sw5x);
        tanh_pack(D, h0h, h0l, own);
        xchg(h0h, h0l, exOwn, exOth, own, oth, barid);

        // layer 1: D = b1 + h1@Whh1^T + h0@Wih1^T
        #pragma unroll
        for (int nt = 0; nt < 8; nt++) {
            float2 bv = *(const float2*)&b1s[jh * 64 + nt * 8 + p * 2];
            D[nt][0] = bv.x; D[nt][1] = bv.y; D[nt][2] = bv.x; D[nt][3] = bv.y;
        }
        if (t > 0) gemm3h(D, h1h, h1l, WHH, WHL, hsR, sw56);
        gemm3h(D, h0h, h0l, WIH, WIL, hsR, sw56);
        if (t < Tq - 1) {
            tanh_pack(D, h1h, h1l, own);
            xchg(h1h, h1l, exOwn, exOth, own, oth, barid);
        } else {
            #pragma unroll
            for (int nt = 0; nt < 8; nt++)
                #pragma unroll
                for (int q = 0; q < 4; q++) D[nt][q] = tanh_fast(D[nt][q]);
        }
    }

    // ---- FC: out = h1 @ fc_w^T + fc_b ----
    __syncthreads();
    float* fcs  = (float*)(dyn + OFF_EX);
    float* part = (float*)(dyn + OFF_PART);
    for (int i = tid; i < Cq * Hq; i += 256) fcs[i] = fc_w[i];
    __syncthreads();

    float accA[Cq], accB[Cq];
    #pragma unroll
    for (int c = 0; c < Cq; c++) { accA[c] = 0.f; accB[c] = 0.f; }
    #pragma unroll
    for (int nt = 0; nt < 8; nt++) {
        int j = jh * 64 + nt * 8 + p * 2;
        #pragma unroll
        for (int c = 0; c < Cq; c++) {
            float2 fw = *(const float2*)&fcs[c * Hq + j];
            accA[c] = fmaf(D[nt][0], fw.x, fmaf(D[nt][1], fw.y, accA[c]));
            accB[c] = fmaf(D[nt][2], fw.x, fmaf(D[nt][3], fw.y, accB[c]));
        }
    }
    #pragma unroll
    for (int c = 0; c < Cq; c++) {
        accA[c] += __shfl_xor_sync(0xFFFFFFFFu, accA[c], 1);
        accA[c] += __shfl_xor_sync(0xFFFFFFFFu, accA[c], 2);
        accB[c] += __shfl_xor_sync(0xFFFFFFFFu, accB[c], 1);
        accB[c] += __shfl_xor_sync(0xFFFFFFFFu, accB[c], 2);
    }
    if (p == 0) {
        int base = (rg * 2 + jh) * 16;
        #pragma unroll
        for (int c = 0; c < Cq; c++) {
            part[(base + g) * Cq + c]     = accA[c];
            part[(base + g + 8) * Cq + c] = accB[c];
        }
    }
    __syncthreads();
    for (int i = tid; i < 64 * Cq; i += 256) {
        int row = i / Cq, c = i - row * Cq;
        int rg2 = row >> 4, rr = row & 15;
        float v = fc_b[c] + part[((rg2 * 2) * 16 + rr) * Cq + c]
                          + part[((rg2 * 2 + 1) * 16 + rr) * Cq + c];
        out[((size_t)blockIdx.x * 64 + row) * Cq + c] = v;
    }
}

extern "C" void kernel_launch(void* const* d_in, const int* in_sizes, int n_in,
                              void* d_out, int out_size) {
    const float* x     = (const float*)d_in[0];
    const float* W_ih0 = (const float*)d_in[1];
    const float* W_hh0 = (const float*)d_in[2];
    const float* b_ih0 = (const float*)d_in[3];
    const float* b_hh0 = (const float*)d_in[4];
    const float* W_ih1 = (const float*)d_in[5];
    const float* W_hh1 = (const float*)d_in[6];
    const float* b_ih1 = (const float*)d_in[7];
    const float* b_hh1 = (const float*)d_in[8];
    const float* fc_w  = (const float*)d_in[9];
    const float* fc_b  = (const float*)d_in[10];
    float* out = (float*)d_out;

    cudaFuncSetAttribute(rnn_fused, cudaFuncAttributeMaxDynamicSharedMemorySize, SMEM_DYN);
    rnn_fused<<<128, 256, SMEM_DYN>>>(x, W_ih0, W_hh0, b_ih0, b_hh0,
                                      W_ih1, W_hh1, b_ih1, b_hh1, fc_w, fc_b, out);
}

// round 12
// speedup vs baseline: 1.1259x; 1.0366x over previous
#include <cuda_runtime.h>
#include <cuda_bf16.h>

typedef unsigned int u32;

#define Tq 28
#define Iq 28
#define Hq 128
#define Cq 10

// SMEM map (bytes): W0h@0 W0l@32768 WIh@65536 WIl@98304 WHh@131072 WHl@163840 (256B-row swizzle)
// X0h@196608 X0l@204800 (64B-row swizzle) | exch@212992(16K; FC reuse: fcw@212992 part@218112)
// b0@229376 b1@229888
#define OFF_X0H 196608
#define OFF_X0L 204800
#define OFF_EX  212992
#define OFF_PART 218112
#define OFF_B0 229376
#define OFF_B1 229888
#define SMEM_DYN 230400

static __device__ __forceinline__ u32 smem_u32(const void* p) {
    u32 a; asm("{ .reg .u64 t; cvta.to.shared.u64 t, %1; cvt.u32.u64 %0, t; }" : "=r"(a) : "l"(p));
    return a;
}
static __device__ __forceinline__ float tanh_fast(float x) {
    float ax = fabsf(x), e = __expf(-2.f * ax);
    return copysignf(__fdividef(1.f - e, 1.f + e), x);
}
static __device__ __forceinline__ u32 pack_bf16x2(float lo, float hi) {
    u32 r; asm("cvt.rn.bf16x2.f32 %0, %1, %2;" : "=r"(r) : "f"(hi), "f"(lo)); return r;
}
static __device__ __forceinline__ float lo16f(u32 p) { return __uint_as_float(p << 16); }
static __device__ __forceinline__ float hi16f(u32 p) { return __uint_as_float(p & 0xFFFF0000u); }

static __device__ __forceinline__ void mma_bf16(float (&d)[4], const u32 (&a)[4], u32 b0, u32 b1) {
    asm volatile(
        "mma.sync.aligned.m16n8k16.row.col.f32.bf16.bf16.f32 "
        "{%0,%1,%2,%3}, {%4,%5,%6,%7}, {%8,%9}, {%0,%1,%2,%3};"
        : "+f"(d[0]), "+f"(d[1]), "+f"(d[2]), "+f"(d[3])
        : "r"(a[0]), "r"(a[1]), "r"(a[2]), "r"(a[3]), "r"(b0), "r"(b1));
}
#define LDMX4(r0, r1, r2, r3, addr) \
    asm volatile("ldmatrix.sync.aligned.m8n8.x4.shared.b16 {%0,%1,%2,%3}, [%4];" \
        : "=r"(r0), "=r"(r1), "=r"(r2), "=r"(r3) : "r"(addr))
#define STS128(addr, r) \
    asm volatile("st.shared.v4.b32 [%0], {%1,%2,%3,%4};" \
        :: "r"(addr), "r"((r)[0]), "r"((r)[1]), "r"((r)[2]), "r"((r)[3]) : "memory")
#define LDS128(r, addr) \
    asm volatile("ld.shared.v4.b32 {%0,%1,%2,%3}, [%4];" \
        : "=r"((r)[0]), "=r"((r)[1]), "=r"((r)[2]), "=r"((r)[3]) : "r"(addr) : "memory")
#define BARS(id) asm volatile("bar.sync %0, 64;" :: "r"(id) : "memory")

// Software-pipelined: D[8][4] += A(hi,lo) @ W(hi,lo)^T over this warp's 64 j-cols.
// Rolling double-buffer of B-frags: group g+1's LDMX4s issue BEFORE group g's mmas,
// so the ~29cyc LDS latency hides under the 6-mma issue window (asm volatile keeps order).
static __device__ __forceinline__ void gemm3h(float (&D)[8][4],
                                              const u32 (&Ah)[8][4], const u32 (&Al)[8][4],
                                              u32 whb, u32 wlb, u32 hsR, u32 sw56)
{
    u32 bh[2][4], bl[2][4];
    // group g = kt*4+np : addr = ((kt*32)^sw56)+hsR + np*4096
    #define GADDR_R(g) (((u32)((((g) >> 2) * 32)) ^ sw56) + hsR + (u32)(((g) & 3) * 4096))
    LDMX4(bh[0][0], bh[0][1], bh[0][2], bh[0][3], whb + GADDR_R(0));
    LDMX4(bl[0][0], bl[0][1], bl[0][2], bl[0][3], wlb + GADDR_R(0));
    #pragma unroll
    for (int g = 0; g < 32; g++) {
        const int cur = g & 1, nxt = cur ^ 1;
        if (g < 31) {
            u32 a = GADDR_R(g + 1);
            LDMX4(bh[nxt][0], bh[nxt][1], bh[nxt][2], bh[nxt][3], whb + a);
            LDMX4(bl[nxt][0], bl[nxt][1], bl[nxt][2], bl[nxt][3], wlb + a);
        }
        const int kt = g >> 2, np = g & 3;
        mma_bf16(D[2 * np],     Ah[kt], bh[cur][0], bh[cur][1]);
        mma_bf16(D[2 * np],     Al[kt], bh[cur][0], bh[cur][1]);
        mma_bf16(D[2 * np],     Ah[kt], bl[cur][0], bl[cur][1]);
        mma_bf16(D[2 * np + 1], Ah[kt], bh[cur][2], bh[cur][3]);
        mma_bf16(D[2 * np + 1], Al[kt], bh[cur][2], bh[cur][3]);
        mma_bf16(D[2 * np + 1], Ah[kt], bl[cur][2], bl[cur][3]);
    }
    #undef GADDR_R
}
// x GEMM: K=32 (2 k-chunks), 64B-row swizzled X tile, same pipelining (8 groups).
static __device__ __forceinline__ void gemm_x(float (&D)[8][4],
                                              const u32 (&Ah)[2][4], const u32 (&Al)[2][4],
                                              u32 xhb, u32 xlb, u32 hsX, u32 sw5x)
{
    u32 bh[2][4], bl[2][4];
    #define GADDR_X(g) (((u32)((((g) >> 2) * 32)) ^ sw5x) + hsX + (u32)(((g) & 3) * 1024))
    LDMX4(bh[0][0], bh[0][1], bh[0][2], bh[0][3], xhb + GADDR_X(0));
    LDMX4(bl[0][0], bl[0][1], bl[0][2], bl[0][3], xlb + GADDR_X(0));
    #pragma unroll
    for (int g = 0; g < 8; g++) {
        const int cur = g & 1, nxt = cur ^ 1;
        if (g < 7) {
            u32 a = GADDR_X(g + 1);
            LDMX4(bh[nxt][0], bh[nxt][1], bh[nxt][2], bh[nxt][3], xhb + a);
            LDMX4(bl[nxt][0], bl[nxt][1], bl[nxt][2], bl[nxt][3], xlb + a);
        }
        const int kt = g >> 2, np = g & 3;
        mma_bf16(D[2 * np],     Ah[kt], bh[cur][0], bh[cur][1]);
        mma_bf16(D[2 * np],     Al[kt], bh[cur][0], bh[cur][1]);
        mma_bf16(D[2 * np],     Ah[kt], bl[cur][0], bl[cur][1]);
        mma_bf16(D[2 * np + 1], Ah[kt], bh[cur][2], bh[cur][3]);
        mma_bf16(D[2 * np + 1], Al[kt], bh[cur][2], bh[cur][3]);
        mma_bf16(D[2 * np + 1], Ah[kt], bl[cur][2], bl[cur][3]);
    }
    #undef GADDR_X
}
// tanh epilogue: D (own 64 cols) -> hi/lo A-frag chunks [base..base+3]
static __device__ __forceinline__ void tanh_pack(const float (&D)[8][4],
                                                 u32 (&hh)[8][4], u32 (&hl)[8][4], int base)
{
    #pragma unroll
    for (int ktl = 0; ktl < 4; ktl++) {
        #pragma unroll
        for (int o = 0; o < 2; o++) {
            int nt = 2 * ktl + o;
            float v0 = tanh_fast(D[nt][0]), v1 = tanh_fast(D[nt][1]);
            float v2 = tanh_fast(D[nt][2]), v3 = tanh_fast(D[nt][3]);
            u32 p01 = pack_bf16x2(v0, v1), p23 = pack_bf16x2(v2, v3);
            hh[base + ktl][2 * o] = p01;  hh[base + ktl][2 * o + 1] = p23;
            hl[base + ktl][2 * o]     = pack_bf16x2(v0 - lo16f(p01), v1 - hi16f(p01));
            hl[base + ktl][2 * o + 1] = pack_bf16x2(v2 - lo16f(p23), v3 - hi16f(p23));
        }
    }
}
// pairwise hi/lo fragment exchange through SMEM
static __device__ __forceinline__ void xchg(u32 (&hh)[8][4], u32 (&hl)[8][4],
                                            u32 exOwn, u32 exOth, int own, int oth, int barid)
{
    #pragma unroll
    for (int k = 0; k < 4; k++) STS128(exOwn + k * 512, hh[own + k]);
    BARS(barid);
    #pragma unroll
    for (int k = 0; k < 4; k++) LDS128(hh[oth + k], exOth + k * 512);
    BARS(barid);
    #pragma unroll
    for (int k = 0; k < 4; k++) STS128(exOwn + k * 512, hl[own + k]);
    BARS(barid);
    #pragma unroll
    for (int k = 0; k < 4; k++) LDS128(hl[oth + k], exOth + k * 512);
    BARS(barid);
}

__global__ void __launch_bounds__(256, 1) rnn_fused(
    const float* __restrict__ x,
    const float* __restrict__ W_ih0, const float* __restrict__ W_hh0,
    const float* __restrict__ b_ih0, const float* __restrict__ b_hh0,
    const float* __restrict__ W_ih1, const float* __restrict__ W_hh1,
    const float* __restrict__ b_ih1, const float* __restrict__ b_hh1,
    const float* __restrict__ fc_w,  const float* __restrict__ fc_b,
    float* __restrict__ out)
{
    extern __shared__ char dyn[];
    const int tid = threadIdx.x;
    const int wid = tid >> 5, lane = tid & 31;
    const int rg = wid & 3, jh = wid >> 2;   // R9 pairing (measured best)
    const int g = lane >> 2, p = lane & 3;

    // ---- init: W tiles bf16 hi/lo, swizzled ----
    {
        const float* Ws[3] = { W_hh0, W_ih1, W_hh1 };
        #pragma unroll
        for (int m = 0; m < 3; m++) {
            char* dh = dyn + (2 * m) * 32768;
            char* dl = dyn + (2 * m + 1) * 32768;
            const float* W = Ws[m];
            for (int i = tid; i < Hq * Hq; i += 256) {
                int j = i >> 7, k = i & 127;
                float v = W[i];
                __nv_bfloat16 hb = __float2bfloat16(v);
                u32 a = (u32)(j * 256) + (u32)((2 * k) ^ ((j & 7) << 4));
                *(__nv_bfloat16*)(dh + a) = hb;
                *(__nv_bfloat16*)(dl + a) = __float2bfloat16(v - __bfloat162float(hb));
            }
        }
        for (int i = tid; i < Hq * 32; i += 256) {   // X tiles [j][k pad32]
            int j = i >> 5, k = i & 31;
            float v = (k < Iq) ? W_ih0[j * Iq + k] : 0.0f;
            __nv_bfloat16 hb = __float2bfloat16(v);
            u32 a = (u32)(j * 64) + (u32)((2 * k) ^ ((j & 3) << 4));
            *(__nv_bfloat16*)(dyn + OFF_X0H + a) = hb;
            *(__nv_bfloat16*)(dyn + OFF_X0L + a) = __float2bfloat16(v - __bfloat162float(hb));
        }
        float* b0s = (float*)(dyn + OFF_B0);
        float* b1s = (float*)(dyn + OFF_B1);
        for (int i = tid; i < Hq; i += 256) {
            b0s[i] = b_ih0[i] + b_hh0[i];
            b1s[i] = b_ih1[i] + b_hh1[i];
        }
    }
    __syncthreads();

    const u32 smb = smem_u32(dyn);
    const u32 r    = (u32)((((lane >> 4) & 1) * 8) + (lane & 7));
    const u32 h16  = (u32)(((lane >> 3) & 1) * 16);
    const u32 swzR = (u32)((lane & 7) << 4);
    const u32 hsR  = r * 256 + (h16 ^ (swzR & 16));
    const u32 sw56 = swzR & 96;
    const u32 swzX = (u32)((lane & 3) << 4);
    const u32 hsX  = r * 64 + (h16 ^ (swzX & 16));
    const u32 sw5x = swzX & 32;

    const u32 W0H = smb + (u32)(jh * 16384),           W0L = smb + 32768  + (u32)(jh * 16384);
    const u32 WIH = smb + 65536 + (u32)(jh * 16384),   WIL = smb + 98304  + (u32)(jh * 16384);
    const u32 WHH = smb + 131072 + (u32)(jh * 16384),  WHL = smb + 163840 + (u32)(jh * 16384);
    const u32 X0H = smb + OFF_X0H + (u32)(jh * 4096),  X0L = smb + OFF_X0L + (u32)(jh * 4096);
    const u32 exOwn = smb + OFF_EX + (u32)((((rg * 2 + jh) * 4) * 32 + lane) * 16);
    const u32 exOth = smb + OFF_EX + (u32)((((rg * 2 + 1 - jh) * 4) * 32 + lane) * 16);
    const int own = jh * 4, oth = (1 - jh) * 4, barid = rg + 1;

    const float* b0s = (float*)(dyn + OFF_B0);
    const float* b1s = (float*)(dyn + OFF_B1);
    const size_t rowA = ((size_t)blockIdx.x * 4 + rg) * 16 + g;
    const float* xA = x + rowA * Tq * Iq;
    const float* xB = x + (rowA + 8) * Tq * Iq;

    u32 h0h[8][4], h0l[8][4], h1h[8][4], h1l[8][4];
    float D[8][4];

    for (int t = 0; t < Tq; t++) {
        // x A-frags (K=32, rows g/g+8)
        u32 xh[2][4], xl[2][4];
        {
            const float* at = xA + t * Iq;
            const float* bt = xB + t * Iq;
            float2 xv[8];
            xv[0] = *(const float2*)(at + 2 * p);       xv[1] = *(const float2*)(bt + 2 * p);
            xv[2] = *(const float2*)(at + 8 + 2 * p);   xv[3] = *(const float2*)(bt + 8 + 2 * p);
            xv[4] = *(const float2*)(at + 16 + 2 * p);  xv[5] = *(const float2*)(bt + 16 + 2 * p);
            xv[6] = (p < 2) ? *(const float2*)(at + 24 + 2 * p) : make_float2(0.f, 0.f);
            xv[7] = (p < 2) ? *(const float2*)(bt + 24 + 2 * p) : make_float2(0.f, 0.f);
            #pragma unroll
            for (int q = 0; q < 8; q++) {
                u32 hu = pack_bf16x2(xv[q].x, xv[q].y);
                xh[q >> 2][q & 3] = hu;
                xl[q >> 2][q & 3] = pack_bf16x2(xv[q].x - lo16f(hu), xv[q].y - hi16f(hu));
            }
        }

        // layer 0: D = b0 + h0@W0^T + x@Wih0^T
        #pragma unroll
        for (int nt = 0; nt < 8; nt++) {
            float2 bv = *(const float2*)&b0s[jh * 64 + nt * 8 + p * 2];
            D[nt][0] = bv.x; D[nt][1] = bv.y; D[nt][2] = bv.x; D[nt][3] = bv.y;
        }
        if (t > 0) gemm3h(D, h0h, h0l, W0H, W0L, hsR, sw56);
        gemm_x(D, xh, xl, X0H, X0L, hsX, sw5x);
        tanh_pack(D, h0h, h0l, own);
        xchg(h0h, h0l, exOwn, exOth, own, oth, barid);

        // layer 1: D = b1 + h1@Whh1^T + h0@Wih1^T
        #pragma unroll
        for (int nt = 0; nt < 8; nt++) {
            float2 bv = *(const float2*)&b1s[jh * 64 + nt * 8 + p * 2];
            D[nt][0] = bv.x; D[nt][1] = bv.y; D[nt][2] = bv.x; D[nt][3] = bv.y;
        }
        if (t > 0) gemm3h(D, h1h, h1l, WHH, WHL, hsR, sw56);
        gemm3h(D, h0h, h0l, WIH, WIL, hsR, sw56);
        if (t < Tq - 1) {
            tanh_pack(D, h1h, h1l, own);
            xchg(h1h, h1l, exOwn, exOth, own, oth, barid);
        } else {
            #pragma unroll
            for (int nt = 0; nt < 8; nt++)
                #pragma unroll
                for (int q = 0; q < 4; q++) D[nt][q] = tanh_fast(D[nt][q]);
        }
    }

    // ---- FC: out = h1 @ fc_w^T + fc_b ----
    __syncthreads();
    float* fcs  = (float*)(dyn + OFF_EX);
    float* part = (float*)(dyn + OFF_PART);
    for (int i = tid; i < Cq * Hq; i += 256) fcs[i] = fc_w[i];
    __syncthreads();

    float accA[Cq], accB[Cq];
    #pragma unroll
    for (int c = 0; c < Cq; c++) { accA[c] = 0.f; accB[c] = 0.f; }
    #pragma unroll
    for (int nt = 0; nt < 8; nt++) {
        int j = jh * 64 + nt * 8 + p * 2;
        #pragma unroll
        for (int c = 0; c < Cq; c++) {
            float2 fw = *(const float2*)&fcs[c * Hq + j];
            accA[c] = fmaf(D[nt][0], fw.x, fmaf(D[nt][1], fw.y, accA[c]));
            accB[c] = fmaf(D[nt][2], fw.x, fmaf(D[nt][3], fw.y, accB[c]));
        }
    }
    #pragma unroll
    for (int c = 0; c < Cq; c++) {
        accA[c] += __shfl_xor_sync(0xFFFFFFFFu, accA[c], 1);
        accA[c] += __shfl_xor_sync(0xFFFFFFFFu, accA[c], 2);
        accB[c] += __shfl_xor_sync(0xFFFFFFFFu, accB[c], 1);
        accB[c] += __shfl_xor_sync(0xFFFFFFFFu, accB[c], 2);
    }
    if (p == 0) {
        int base = (rg * 2 + jh) * 16;
        #pragma unroll
        for (int c = 0; c < Cq; c++) {
            part[(base + g) * Cq + c]     = accA[c];
            part[(base + g + 8) * Cq + c] = accB[c];
        }
    }
    __syncthreads();
    for (int i = tid; i < 64 * Cq; i += 256) {
        int row = i / Cq, c = i - row * Cq;
        int rg2 = row >> 4, rr = row & 15;
        float v = fc_b[c] + part[((rg2 * 2) * 16 + rr) * Cq + c]
                          + part[((rg2 * 2 + 1) * 16 + rr) * Cq + c];
        out[((size_t)blockIdx.x * 64 + row) * Cq + c] = v;
    }
}

extern "C" void kernel_launch(void* const* d_in, const int* in_sizes, int n_in,
                              void* d_out, int out_size) {
    const float* x     = (const float*)d_in[0];
    const float* W_ih0 = (const float*)d_in[1];
    const float* W_hh0 = (const float*)d_in[2];
    const float* b_ih0 = (const float*)d_in[3];
    const float* b_hh0 = (const float*)d_in[4];
    const float* W_ih1 = (const float*)d_in[5];
    const float* W_hh1 = (const float*)d_in[6];
    const float* b_ih1 = (const float*)d_in[7];
    const float* b_hh1 = (const float*)d_in[8];
    const float* fc_w  = (const float*)d_in[9];
    const float* fc_b  = (const float*)d_in[10];
    float* out = (float*)d_out;

    cudaFuncSetAttribute(rnn_fused, cudaFuncAttributeMaxDynamicSharedMemorySize, SMEM_DYN);
    rnn_fused<<<128, 256, SMEM_DYN>>>(x, W_ih0, W_hh0, b_ih0, b_hh0,
                                      W_ih1, W_hh1, b_ih1, b_hh1, fc_w, fc_b, out);
}